// round 1
// baseline (speedup 1.0000x reference)
#include <cuda_runtime.h>
#include <cuda_bf16.h>

#define NP 512
#define NDIM 3

// One block per batch element. 512 threads, thread t owns particle t.
// Pair coverage by cyclic offset: k = 1..255 for all i, k = 256 for i < 256.
// Covers each unordered pair exactly once (512*511/2 = 130816 pairs), balanced.
// Total LJ sum = 2 * (sum over unordered pairs).
__global__ __launch_bounds__(NP, 1)
void lj_osc_kernel(const float* __restrict__ x, float* __restrict__ out) {
    __shared__ float xs[NP];
    __shared__ float ys[NP];
    __shared__ float zs[NP];
    __shared__ float red[5][16];

    const int b = blockIdx.x;
    const int t = threadIdx.x;
    const float* __restrict__ xb = x + (size_t)b * (NP * NDIM);

    // Coalesced load of 1536 floats, scatter into SoA shared arrays.
    {
        float v0 = xb[t];
        float v1 = xb[t + 512];
        float v2 = xb[t + 1024];
        int e, p, d;
        e = t;        p = e / 3; d = e - 3 * p;
        ((d == 0) ? xs : (d == 1) ? ys : zs)[p] = v0;
        e = t + 512;  p = e / 3; d = e - 3 * p;
        ((d == 0) ? xs : (d == 1) ? ys : zs)[p] = v1;
        e = t + 1024; p = e / 3; d = e - 3 * p;
        ((d == 0) ? xs : (d == 1) ? ys : zs)[p] = v2;
    }
    __syncthreads();

    const float xi = xs[t];
    const float yi = ys[t];
    const float zi = zs[t];

    float acc = 0.0f;

    // Main pair loop: offsets 1..255
    #pragma unroll 8
    for (int k = 1; k < 256; ++k) {
        int j = (t + k) & (NP - 1);
        float dx = xi - xs[j];
        float dy = yi - ys[j];
        float dz = zi - zs[j];
        float s = fmaf(dx, dx, fmaf(dy, dy, fmaf(dz, dz, 1e-6f)));
        // fast reciprocal: bit-hack seed + 2 Newton iterations (avoids MUFU)
        float y = __uint_as_float(0x7EF311C3u - __float_as_uint(s));
        y = y * fmaf(-s, y, 2.0f);
        y = y * fmaf(-s, y, 2.0f);
        float i6 = y * y * y;              // (d2+eps)^-3  ==  (rm/r)^6
        acc = fmaf(i6, i6 - 2.0f, acc);    // inv12 - 2*inv6
    }
    // Offset 256: only for i < 256 (each such pair appears once)
    if (t < 256) {
        int j = t + 256;
        float dx = xi - xs[j];
        float dy = yi - ys[j];
        float dz = zi - zs[j];
        float s = fmaf(dx, dx, fmaf(dy, dy, fmaf(dz, dz, 1e-6f)));
        float y = __uint_as_float(0x7EF311C3u - __float_as_uint(s));
        y = y * fmaf(-s, y, 2.0f);
        y = y * fmaf(-s, y, 2.0f);
        float i6 = y * y * y;
        acc = fmaf(i6, i6 - 2.0f, acc);
    }

    // Oscillator contributions for this particle
    float ssq = fmaf(xi, xi, fmaf(yi, yi, zi * zi));

    // Block reduction of 5 values: acc(LJ), sum_x, sum_y, sum_z, sum_sq
    float v[5] = {acc, xi, yi, zi, ssq};
    const unsigned FULL = 0xFFFFFFFFu;
    #pragma unroll
    for (int q = 0; q < 5; ++q) {
        float r = v[q];
        r += __shfl_down_sync(FULL, r, 16);
        r += __shfl_down_sync(FULL, r, 8);
        r += __shfl_down_sync(FULL, r, 4);
        r += __shfl_down_sync(FULL, r, 2);
        r += __shfl_down_sync(FULL, r, 1);
        v[q] = r;
    }
    const int warp = t >> 5;
    const int lane = t & 31;
    if (lane == 0) {
        #pragma unroll
        for (int q = 0; q < 5; ++q) red[q][warp] = v[q];
    }
    __syncthreads();
    if (warp == 0) {
        float r[5];
        #pragma unroll
        for (int q = 0; q < 5; ++q) {
            float val = (lane < 16) ? red[q][lane] : 0.0f;
            val += __shfl_down_sync(FULL, val, 8);
            val += __shfl_down_sync(FULL, val, 4);
            val += __shfl_down_sync(FULL, val, 2);
            val += __shfl_down_sync(FULL, val, 1);
            r[q] = val;
        }
        if (lane == 0) {
            float lj_total = 2.0f * r[0];
            float mean_sq = (r[1] * r[1] + r[2] * r[2] + r[3] * r[3]) * (1.0f / NP);
            float osc = 0.5f * (r[4] - mean_sq);
            out[b] = lj_total + osc;
        }
    }
}

extern "C" void kernel_launch(void* const* d_in, const int* in_sizes, int n_in,
                              void* d_out, int out_size) {
    const float* x = (const float*)d_in[0];
    float* out = (float*)d_out;
    int batches = in_sizes[0] / (NP * NDIM);   // 128
    lj_osc_kernel<<<batches, NP>>>(x, out);
}

// round 2
// speedup vs baseline: 1.0308x; 1.0308x over previous
#include <cuda_runtime.h>
#include <cuda_bf16.h>

#define NP 512

typedef unsigned long long u64;

// ---- packed f32x2 helpers (SASS FFMA2/FADD2/FMUL2 — only reachable via PTX) ----
__device__ __forceinline__ u64 pk2(float lo, float hi) {
    u64 r; asm("mov.b64 %0,{%1,%2};" : "=l"(r) : "f"(lo), "f"(hi)); return r;
}
__device__ __forceinline__ u64 fma2(u64 a, u64 b, u64 c) {
    u64 d; asm("fma.rn.f32x2 %0,%1,%2,%3;" : "=l"(d) : "l"(a), "l"(b), "l"(c)); return d;
}
__device__ __forceinline__ u64 add2(u64 a, u64 b) {
    u64 d; asm("add.rn.f32x2 %0,%1,%2;" : "=l"(d) : "l"(a), "l"(b)); return d;
}
__device__ __forceinline__ u64 mul2(u64 a, u64 b) {
    u64 d; asm("mul.rn.f32x2 %0,%1,%2;" : "=l"(d) : "l"(a), "l"(b)); return d;
}
// bit-hack reciprocal seed on both packed halves (2 IADD on the alu pipe)
__device__ __forceinline__ u64 rcpseed2(u64 s) {
    u64 d;
    asm("{ .reg .b32 lo,hi;\n\t"
        "  mov.b64 {lo,hi}, %1;\n\t"
        "  sub.u32 lo, 0x7EF311C3, lo;\n\t"
        "  sub.u32 hi, 0x7EF311C3, hi;\n\t"
        "  mov.b64 %0, {lo,hi}; }" : "=l"(d) : "l"(s));
    return d;
}

// scalar LJ pair contribution (tail iterations only)
__device__ __forceinline__ float lj_pair(float dx, float dy, float dz) {
    float s = fmaf(dx, dx, fmaf(dy, dy, fmaf(dz, dz, 1e-6f)));
    float y = __uint_as_float(0x7EF311C3u - __float_as_uint(s));
    y = y * fmaf(-s, y, 2.0f);
    y = y * fmaf(-s, y, 2.0f);
    float i6 = y * y * y;
    return i6 * (i6 - 2.0f);
}

// One block per batch element; 512 threads, thread t owns particle t.
// Unordered-pair coverage via cyclic offsets k=1..255 (all t) + k=256 (t<256).
// Offsets packed two-at-a-time into f32x2 lanes: (k, k+128) for k=1..127;
// tails k=128 (all t) and k=256 (t<256) done scalar.
// Shared arrays duplicated to 1024 entries so j = t+k never wraps (no AND).
__global__ __launch_bounds__(NP, 1)
void lj_osc_kernel(const float* __restrict__ x, float* __restrict__ out) {
    __shared__ float xs[2 * NP];
    __shared__ float ys[2 * NP];
    __shared__ float zs[2 * NP];
    __shared__ float red[5][16];

    const int b = blockIdx.x;
    const int t = threadIdx.x;
    const float* __restrict__ xb = x + (size_t)b * (NP * 3);

    // Coalesced load of 1536 floats, scatter into duplicated SoA shared arrays.
    {
        float v0 = xb[t];
        float v1 = xb[t + 512];
        float v2 = xb[t + 1024];
        int e, p, d;
        e = t;        p = e / 3; d = e - 3 * p;
        { float* a = (d == 0) ? xs : (d == 1) ? ys : zs; a[p] = v0; a[p + NP] = v0; }
        e = t + 512;  p = e / 3; d = e - 3 * p;
        { float* a = (d == 0) ? xs : (d == 1) ? ys : zs; a[p] = v1; a[p + NP] = v1; }
        e = t + 1024; p = e / 3; d = e - 3 * p;
        { float* a = (d == 0) ? xs : (d == 1) ? ys : zs; a[p] = v2; a[p + NP] = v2; }
    }
    __syncthreads();

    const float xi = xs[t];
    const float yi = ys[t];
    const float zi = zs[t];

    const u64 nxi = pk2(-xi, -xi);
    const u64 nyi = pk2(-yi, -yi);
    const u64 nzi = pk2(-zi, -zi);
    const u64 EPS  = pk2(1e-6f, 1e-6f);
    const u64 TWO  = pk2(2.0f, 2.0f);
    const u64 NEG1 = pk2(-1.0f, -1.0f);
    const u64 NEG2 = pk2(-2.0f, -2.0f);

    u64 acc2 = pk2(0.0f, 0.0f);

    // Main packed loop: lanes (k, k+128) for k = 1..127  (254 offsets)
    #pragma unroll 4
    for (int k = 1; k < 128; ++k) {
        int j = t + k;                 // j in [1, 638]; j+128 in [129, 766]
        u64 xj = pk2(xs[j], xs[j + 128]);
        u64 yj = pk2(ys[j], ys[j + 128]);
        u64 zj = pk2(zs[j], zs[j + 128]);
        u64 dx = add2(xj, nxi);
        u64 dy = add2(yj, nyi);
        u64 dz = add2(zj, nzi);
        u64 s  = fma2(dx, dx, fma2(dy, dy, fma2(dz, dz, EPS)));
        u64 y  = rcpseed2(s);
        u64 sn = mul2(s, NEG1);
        y = mul2(y, fma2(sn, y, TWO));
        y = mul2(y, fma2(sn, y, TWO));
        u64 i6 = mul2(mul2(y, y), y);
        acc2 = fma2(i6, add2(i6, NEG2), acc2);
    }

    // Unpack packed accumulator (both lanes are the same batch)
    float al, ah;
    asm("mov.b64 {%0,%1}, %2;" : "=f"(al), "=f"(ah) : "l"(acc2));
    float acc = al + ah;

    // Tail k = 128 (all threads)
    {
        int j = t + 128;
        acc += lj_pair(xi - xs[j], yi - ys[j], zi - zs[j]);
    }
    // Tail k = 256 (t < 256 only)
    if (t < 256) {
        int j = t + 256;
        acc += lj_pair(xi - xs[j], yi - ys[j], zi - zs[j]);
    }

    // Oscillator per-particle terms
    float ssq = fmaf(xi, xi, fmaf(yi, yi, zi * zi));

    // Block reduction of 5 values: acc(LJ), sum_x, sum_y, sum_z, sum_sq
    float v[5] = {acc, xi, yi, zi, ssq};
    const unsigned FULL = 0xFFFFFFFFu;
    #pragma unroll
    for (int q = 0; q < 5; ++q) {
        float r = v[q];
        r += __shfl_down_sync(FULL, r, 16);
        r += __shfl_down_sync(FULL, r, 8);
        r += __shfl_down_sync(FULL, r, 4);
        r += __shfl_down_sync(FULL, r, 2);
        r += __shfl_down_sync(FULL, r, 1);
        v[q] = r;
    }
    const int warp = t >> 5;
    const int lane = t & 31;
    if (lane == 0) {
        #pragma unroll
        for (int q = 0; q < 5; ++q) red[q][warp] = v[q];
    }
    __syncthreads();
    if (warp == 0) {
        float r[5];
        #pragma unroll
        for (int q = 0; q < 5; ++q) {
            float val = (lane < 16) ? red[q][lane] : 0.0f;
            val += __shfl_down_sync(FULL, val, 8);
            val += __shfl_down_sync(FULL, val, 4);
            val += __shfl_down_sync(FULL, val, 2);
            val += __shfl_down_sync(FULL, val, 1);
            r[q] = val;
        }
        if (lane == 0) {
            float lj_total = 2.0f * r[0];
            float mean_sq = (r[1] * r[1] + r[2] * r[2] + r[3] * r[3]) * (1.0f / NP);
            float osc = 0.5f * (r[4] - mean_sq);
            out[b] = lj_total + osc;
        }
    }
}

extern "C" void kernel_launch(void* const* d_in, const int* in_sizes, int n_in,
                              void* d_out, int out_size) {
    const float* x = (const float*)d_in[0];
    float* out = (float*)d_out;
    int batches = in_sizes[0] / (NP * 3);   // 128
    lj_osc_kernel<<<batches, NP>>>(x, out);
}

// round 3
// speedup vs baseline: 1.1555x; 1.1210x over previous
#include <cuda_runtime.h>
#include <cuda_bf16.h>

#define NP 512

typedef unsigned long long u64;

// ---- packed f32x2 helpers (SASS FFMA2/FADD2/FMUL2 — only reachable via PTX) ----
__device__ __forceinline__ u64 pk2(float lo, float hi) {
    u64 r; asm("mov.b64 %0,{%1,%2};" : "=l"(r) : "f"(lo), "f"(hi)); return r;
}
__device__ __forceinline__ u64 fma2(u64 a, u64 b, u64 c) {
    u64 d; asm("fma.rn.f32x2 %0,%1,%2,%3;" : "=l"(d) : "l"(a), "l"(b), "l"(c)); return d;
}
__device__ __forceinline__ u64 add2(u64 a, u64 b) {
    u64 d; asm("add.rn.f32x2 %0,%1,%2;" : "=l"(d) : "l"(a), "l"(b)); return d;
}
__device__ __forceinline__ u64 mul2(u64 a, u64 b) {
    u64 d; asm("mul.rn.f32x2 %0,%1,%2;" : "=l"(d) : "l"(a), "l"(b)); return d;
}
// sign-flip both packed lanes on the ALU pipe (2x LOP3, keeps fma pipe free)
__device__ __forceinline__ u64 neg2(u64 a) { return a ^ 0x8000000080000000ULL; }
// bit-hack reciprocal seed on both packed halves (2 IADD on the alu pipe)
__device__ __forceinline__ u64 rcpseed2(u64 s) {
    u64 d;
    asm("{ .reg .b32 lo,hi;\n\t"
        "  mov.b64 {lo,hi}, %1;\n\t"
        "  sub.u32 lo, 0x7EF311C3, lo;\n\t"
        "  sub.u32 hi, 0x7EF311C3, hi;\n\t"
        "  mov.b64 %0, {lo,hi}; }" : "=l"(d) : "l"(s));
    return d;
}

// One block per batch element; 512 threads, thread t owns particle t.
// Unordered-pair coverage (each pair exactly once, uniform across threads):
//   packed units (k, k+128) for k = 1..127   -> offsets 1..127, 129..255
//   final packed unit lanes (128, 256) with per-lane weights (1, 1/2)
//     (offset-256 pairs are seen by BOTH endpoints, so each gets weight 1/2)
// Four independent accumulator chains give the ILP needed to saturate the
// fma pipe with only 4 warps/SMSP.
__global__ __launch_bounds__(NP, 1)
void lj_osc_kernel(const float* __restrict__ x, float* __restrict__ out) {
    __shared__ float xs[2 * NP];
    __shared__ float ys[2 * NP];
    __shared__ float zs[2 * NP];
    __shared__ float red[5][16];

    const int b = blockIdx.x;
    const int t = threadIdx.x;
    const float* __restrict__ xb = x + (size_t)b * (NP * 3);

    // Coalesced load of 1536 floats, scatter into duplicated SoA shared arrays.
    {
        float v0 = xb[t];
        float v1 = xb[t + 512];
        float v2 = xb[t + 1024];
        int e, p, d;
        e = t;        p = e / 3; d = e - 3 * p;
        { float* a = (d == 0) ? xs : (d == 1) ? ys : zs; a[p] = v0; a[p + NP] = v0; }
        e = t + 512;  p = e / 3; d = e - 3 * p;
        { float* a = (d == 0) ? xs : (d == 1) ? ys : zs; a[p] = v1; a[p + NP] = v1; }
        e = t + 1024; p = e / 3; d = e - 3 * p;
        { float* a = (d == 0) ? xs : (d == 1) ? ys : zs; a[p] = v2; a[p + NP] = v2; }
    }
    __syncthreads();

    const float xi = xs[t];
    const float yi = ys[t];
    const float zi = zs[t];

    const u64 nxi  = pk2(-xi, -xi);
    const u64 nyi  = pk2(-yi, -yi);
    const u64 nzi  = pk2(-zi, -zi);
    const u64 EPS  = pk2(1e-6f, 1e-6f);
    const u64 TWO  = pk2(2.0f, 2.0f);
    const u64 NEG2 = pk2(-2.0f, -2.0f);
    const u64 WHAL = pk2(1.0f, 0.5f);   // weights for final (128,256) unit

    u64 a0 = 0, a1 = 0, a2 = 0, a3 = 0;

// One packed unit: offsets (K, K+128), accumulate i6*(i6-2) into ACC.
#define UNIT(ACC, K) {                                                   \
        int j = t + (K);                                                 \
        u64 xj = pk2(xs[j], xs[j + 128]);                                \
        u64 yj = pk2(ys[j], ys[j + 128]);                                \
        u64 zj = pk2(zs[j], zs[j + 128]);                                \
        u64 dx = add2(xj, nxi);                                          \
        u64 dy = add2(yj, nyi);                                          \
        u64 dz = add2(zj, nzi);                                          \
        u64 s  = fma2(dx, dx, fma2(dy, dy, fma2(dz, dz, EPS)));          \
        u64 yv = rcpseed2(s);                                            \
        u64 sn = neg2(s);                                                \
        yv = mul2(yv, fma2(sn, yv, TWO));                                \
        yv = mul2(yv, fma2(sn, yv, TWO));                                \
        u64 i6 = mul2(mul2(yv, yv), yv);                                 \
        ACC = fma2(i6, add2(i6, NEG2), ACC); }

    // Four interleaved independent chains: k = 1+m, 33+m, 65+m, 97+m
    for (int m = 0; m < 31; ++m) {
        UNIT(a0, 1 + m);
        UNIT(a1, 33 + m);
        UNIT(a2, 65 + m);
        UNIT(a3, 97 + m);
    }
    // m = 31 for the first three chains
    UNIT(a0, 32);
    UNIT(a1, 64);
    UNIT(a2, 96);
    // Final unit: lanes (128, 256) with weights (1, 1/2)
    {
        int j = t + 128;
        u64 xj = pk2(xs[j], xs[j + 128]);
        u64 yj = pk2(ys[j], ys[j + 128]);
        u64 zj = pk2(zs[j], zs[j + 128]);
        u64 dx = add2(xj, nxi);
        u64 dy = add2(yj, nyi);
        u64 dz = add2(zj, nzi);
        u64 s  = fma2(dx, dx, fma2(dy, dy, fma2(dz, dz, EPS)));
        u64 yv = rcpseed2(s);
        u64 sn = neg2(s);
        yv = mul2(yv, fma2(sn, yv, TWO));
        yv = mul2(yv, fma2(sn, yv, TWO));
        u64 i6 = mul2(mul2(yv, yv), yv);
        u64 term = mul2(i6, add2(i6, NEG2));
        a3 = fma2(term, WHAL, a3);
    }
#undef UNIT

    u64 accp = add2(add2(a0, a1), add2(a2, a3));
    float al, ah;
    asm("mov.b64 {%0,%1}, %2;" : "=f"(al), "=f"(ah) : "l"(accp));
    float acc = al + ah;

    // Oscillator per-particle terms
    float ssq = fmaf(xi, xi, fmaf(yi, yi, zi * zi));

    // Block reduction of 5 values: acc(LJ), sum_x, sum_y, sum_z, sum_sq
    float v[5] = {acc, xi, yi, zi, ssq};
    const unsigned FULL = 0xFFFFFFFFu;
    #pragma unroll
    for (int q = 0; q < 5; ++q) {
        float r = v[q];
        r += __shfl_down_sync(FULL, r, 16);
        r += __shfl_down_sync(FULL, r, 8);
        r += __shfl_down_sync(FULL, r, 4);
        r += __shfl_down_sync(FULL, r, 2);
        r += __shfl_down_sync(FULL, r, 1);
        v[q] = r;
    }
    const int warp = t >> 5;
    const int lane = t & 31;
    if (lane == 0) {
        #pragma unroll
        for (int q = 0; q < 5; ++q) red[q][warp] = v[q];
    }
    __syncthreads();
    if (warp == 0) {
        float r[5];
        #pragma unroll
        for (int q = 0; q < 5; ++q) {
            float val = (lane < 16) ? red[q][lane] : 0.0f;
            val += __shfl_down_sync(FULL, val, 8);
            val += __shfl_down_sync(FULL, val, 4);
            val += __shfl_down_sync(FULL, val, 2);
            val += __shfl_down_sync(FULL, val, 1);
            r[q] = val;
        }
        if (lane == 0) {
            float lj_total = 2.0f * r[0];
            float mean_sq = (r[1] * r[1] + r[2] * r[2] + r[3] * r[3]) * (1.0f / NP);
            float osc = 0.5f * (r[4] - mean_sq);
            out[b] = lj_total + osc;
        }
    }
}

extern "C" void kernel_launch(void* const* d_in, const int* in_sizes, int n_in,
                              void* d_out, int out_size) {
    const float* x = (const float*)d_in[0];
    float* out = (float*)d_out;
    int batches = in_sizes[0] / (NP * 3);   // 128
    lj_osc_kernel<<<batches, NP>>>(x, out);
}